// round 6
// baseline (speedup 1.0000x reference)
#include <cuda_runtime.h>
#include <cuda_fp16.h>

constexpr int B = 1024, F = 784, D = 512;
constexpr int TB = 64, TD = 64, TF = 112;    // 784 = 7 * 112
constexpr int SXH = 120;                      // smem stride in halfs: 240B (odd 16B-chunk count)
constexpr int NSTEP = F / TF;                 // 7
constexpr int NTHR = 512;

union U4H {
    uint4 u;
    __half2 h[4];
};

__device__ __forceinline__ unsigned h2u(__half2 v) {
    union { __half2 h; unsigned u; } c; c.h = v; return c.u;
}

__global__ __launch_bounds__(NTHR)
void dendral_kernel(const float* __restrict__ x,
                    const float* __restrict__ wmin,
                    const float* __restrict__ wmax,
                    float* __restrict__ out)
{
    __shared__ __half sx [TB * SXH];
    __shared__ __half smn[TD * SXH];
    __shared__ __half smx[TD * SXH];

    const int tid = threadIdx.x;
    const int tx  = tid & 15;     // d lane (16)
    const int ty  = tid >> 4;     // b lane (32)
    const int d0  = blockIdx.x * TD;
    const int b0  = blockIdx.y * TB;

    const __half2 INF2 = __halves2half2(__ushort_as_half(0x7C00), __ushort_as_half(0x7C00));
    __half2 acc[4][2];           // i: 4 d-frags, j: 2 b-frags
    #pragma unroll
    for (int i = 0; i < 4; ++i)
        #pragma unroll
        for (int j = 0; j < 2; ++j) acc[i][j] = INF2;

    for (int k = 0; k < NSTEP; ++k) {
        const int f0 = k * TF;
        __syncthreads();

        // Stage + convert fp32->fp16: 64 rows x 28 float4 = 1792 float4 per array.
        #pragma unroll
        for (int t = 0; t < 4; ++t) {
            int idx = tid + t * NTHR;
            if (idx < 1792) {
                int row = idx / 28;
                int c4  = idx % 28;

                float4 vx = *(const float4*)&x   [(b0 + row) * F + f0 + c4 * 4];
                float4 vn = *(const float4*)&wmin[(d0 + row) * F + f0 + c4 * 4];
                float4 vm = *(const float4*)&wmax[(d0 + row) * F + f0 + c4 * 4];

                int so = row * SXH + c4 * 4;
                *(uint2*)&sx [so] = make_uint2(h2u(__floats2half2_rn(vx.x, vx.y)),
                                               h2u(__floats2half2_rn(vx.z, vx.w)));
                *(uint2*)&smn[so] = make_uint2(h2u(__floats2half2_rn(vn.x, vn.y)),
                                               h2u(__floats2half2_rn(vn.z, vn.w)));
                *(uint2*)&smx[so] = make_uint2(h2u(__floats2half2_rn(vm.x, vm.y)),
                                               h2u(__floats2half2_rn(vm.z, vm.w)));
            }
        }
        __syncthreads();

        #pragma unroll 2
        for (int f = 0; f < TF; f += 8) {
            U4H xv[2];
            #pragma unroll
            for (int j = 0; j < 2; ++j)
                xv[j].u = *(const uint4*)&sx[(ty + 32 * j) * SXH + f];

            #pragma unroll
            for (int i = 0; i < 4; ++i) {
                U4H nv, mv;
                nv.u = *(const uint4*)&smn[(tx + 16 * i) * SXH + f];
                mv.u = *(const uint4*)&smx[(tx + 16 * i) * SXH + f];
                #pragma unroll
                for (int j = 0; j < 2; ++j) {
                    __half2 c0 = __hmin2(__hsub2(xv[j].h[0], nv.h[0]), __hsub2(mv.h[0], xv[j].h[0]));
                    __half2 c1 = __hmin2(__hsub2(xv[j].h[1], nv.h[1]), __hsub2(mv.h[1], xv[j].h[1]));
                    __half2 c2 = __hmin2(__hsub2(xv[j].h[2], nv.h[2]), __hsub2(mv.h[2], xv[j].h[2]));
                    __half2 c3 = __hmin2(__hsub2(xv[j].h[3], nv.h[3]), __hsub2(mv.h[3], xv[j].h[3]));
                    __half2 d01 = __hmin2(c0, c1);
                    __half2 d23 = __hmin2(c2, c3);
                    acc[i][j] = __hmin2(acc[i][j], __hmin2(d01, d23));
                }
            }
        }
    }

    // Epilogue: min the two half lanes (two f's), store fp32.
    #pragma unroll
    for (int i = 0; i < 4; ++i)
        #pragma unroll
        for (int j = 0; j < 2; ++j) {
            float lo = __low2float (acc[i][j]);
            float hi = __high2float(acc[i][j]);
            int b = b0 + ty + 32 * j;
            int d = d0 + tx + 16 * i;
            out[b * D + d] = fminf(lo, hi);
        }
}

extern "C" void kernel_launch(void* const* d_in, const int* in_sizes, int n_in,
                              void* d_out, int out_size)
{
    const float* x    = (const float*)d_in[0];
    const float* wmin = (const float*)d_in[1];
    const float* wmax = (const float*)d_in[2];
    float* out = (float*)d_out;

    dim3 grid(D / TD, B / TB);   // (8, 16) = 128 CTAs
    dendral_kernel<<<grid, NTHR>>>(x, wmin, wmax, out);
}